// round 1
// baseline (speedup 1.0000x reference)
#include <cuda_runtime.h>
#include <math.h>
#include <float.h>

#define B_ 2
#define T_ 2048
#define E_ 2048
#define H_ 32
#define G_ 8
#define D_ 64
#define S_ 2048
#define F_ 3072            // (H + 2G) * D
#define EPSV 1e-6f

// ---------------- scratch (device globals: allocation-free) ----------------
__device__ float g_qkv[(size_t)B_ * T_ * F_];        // 4096 x 3072
__device__ float g_o[(size_t)B_ * T_ * H_ * D_];     // 4096 x 2048

// ---------------- generic SGEMM: C(MxN) = A(MxK) * B(NxK)^T, row-major ----
// 128x128 tile, BK=8, 256 threads, 8x8 micro-tile per thread.
__global__ __launch_bounds__(256) void sgemm_nt(const float* __restrict__ A,
                                                const float* __restrict__ B,
                                                float* __restrict__ C,
                                                int M, int N, int K) {
    __shared__ float As[8][128];
    __shared__ float Bs[8][128];
    const int tid = threadIdx.x;
    const int tx = tid & 15;
    const int ty = tid >> 4;
    const int mBase = blockIdx.y * 128;
    const int nBase = blockIdx.x * 128;
    const int lRow = tid >> 1;          // 0..127
    const int lCol = (tid & 1) * 4;     // 0 or 4
    const float* Ap = A + (size_t)(mBase + lRow) * K + lCol;
    const float* Bp = B + (size_t)(nBase + lRow) * K + lCol;

    float acc[8][8];
#pragma unroll
    for (int i = 0; i < 8; i++)
#pragma unroll
        for (int j = 0; j < 8; j++) acc[i][j] = 0.0f;

    for (int k0 = 0; k0 < K; k0 += 8) {
        float4 av = *(const float4*)(Ap + k0);
        float4 bv = *(const float4*)(Bp + k0);
        As[lCol + 0][lRow] = av.x;
        As[lCol + 1][lRow] = av.y;
        As[lCol + 2][lRow] = av.z;
        As[lCol + 3][lRow] = av.w;
        Bs[lCol + 0][lRow] = bv.x;
        Bs[lCol + 1][lRow] = bv.y;
        Bs[lCol + 2][lRow] = bv.z;
        Bs[lCol + 3][lRow] = bv.w;
        __syncthreads();
#pragma unroll
        for (int kk = 0; kk < 8; kk++) {
            float4 a0 = *(const float4*)&As[kk][ty * 8];
            float4 a1 = *(const float4*)&As[kk][ty * 8 + 4];
            float4 b0 = *(const float4*)&Bs[kk][tx * 8];
            float4 b1 = *(const float4*)&Bs[kk][tx * 8 + 4];
            float a[8] = {a0.x, a0.y, a0.z, a0.w, a1.x, a1.y, a1.z, a1.w};
            float b[8] = {b0.x, b0.y, b0.z, b0.w, b1.x, b1.y, b1.z, b1.w};
#pragma unroll
            for (int i = 0; i < 8; i++)
#pragma unroll
                for (int j = 0; j < 8; j++) acc[i][j] += a[i] * b[j];
        }
        __syncthreads();
    }

#pragma unroll
    for (int i = 0; i < 8; i++) {
        float* Cp = C + (size_t)(mBase + ty * 8 + i) * N + nBase + tx * 8;
        *(float4*)(Cp + 0) = make_float4(acc[i][0], acc[i][1], acc[i][2], acc[i][3]);
        *(float4*)(Cp + 4) = make_float4(acc[i][4], acc[i][5], acc[i][6], acc[i][7]);
    }
}

// ---------------- RMSNorm + RoPE + cache scatter ----------------
// One block per (b,t). 8 warps; warp w handles heads w, w+8, ... (48 heads).
// Q heads (0..31): rmsnorm(q_norm_w) + rope, write back into g_qkv.
// K heads (32..39): rmsnorm(k_norm_w) + rope, scatter to cache_k[b, pos[t], g].
// V heads (40..47): raw copy to cache_v[b, pos[t], g].
__global__ __launch_bounds__(256) void rmsrope_kernel(
    float* __restrict__ qkv, const float* __restrict__ qw,
    const float* __restrict__ kw, const float* __restrict__ cosb,
    const float* __restrict__ sinb, const int* __restrict__ pos,
    float* __restrict__ ck, float* __restrict__ cv) {
    const int bt = blockIdx.x;
    const int b = bt / T_;
    const int t = bt % T_;
    const int lane = threadIdx.x & 31;
    const int w = threadIdx.x >> 5;
    const int p = pos[t];
    const float c = cosb[t * 32 + lane];
    const float s = sinb[t * 32 + lane];
    float* base = qkv + (size_t)bt * F_;

    for (int hh = w; hh < 48; hh += 8) {
        float* v = base + hh * 64;
        float x1 = v[lane];
        float x2 = v[lane + 32];
        if (hh < 40) {
            float ss = x1 * x1 + x2 * x2;
#pragma unroll
            for (int off = 16; off >= 1; off >>= 1)
                ss += __shfl_xor_sync(0xffffffffu, ss, off);
            float inv = rsqrtf(ss * (1.0f / 64.0f) + EPSV);
            const float* wgt = (hh < 32) ? qw : kw;
            float n1 = x1 * inv * wgt[lane];
            float n2 = x2 * inv * wgt[lane + 32];
            float r1 = n1 * c - n2 * s;
            float r2 = n2 * c + n1 * s;
            if (hh < 32) {
                v[lane] = r1;
                v[lane + 32] = r2;
            } else {
                float* dst = ck + (((size_t)b * S_ + p) * G_ + (hh - 32)) * 64;
                dst[lane] = r1;
                dst[lane + 32] = r2;
            }
        } else {
            float* dst = cv + (((size_t)b * S_ + p) * G_ + (hh - 40)) * 64;
            dst[lane] = x1;
            dst[lane + 32] = x2;
        }
    }
}

// ---------------- Flash attention (fp32) ----------------
// grid: (T/64, H, B). 256 threads. 64-query x 64-key tiles, online softmax.
// Dynamic smem: Qs[64*64] + KV[64*68] + Ps[64*64] = 50176 bytes.
#define KVROW 68
__global__ __launch_bounds__(256) void attn_kernel(
    const float* __restrict__ qkv, const float* __restrict__ ck,
    const float* __restrict__ cv, const float* __restrict__ mask,
    float* __restrict__ o) {
    extern __shared__ float sm[];
    float* Qs = sm;                 // [64][64]
    float* KV = sm + 64 * 64;       // [64][68] holds K then V per chunk
    float* Ps = KV + 64 * KVROW;    // [64][64]

    const int qt = blockIdx.x;
    const int h = blockIdx.y;
    const int b = blockIdx.z;
    const int g = h >> 2;           // H/G = 4 q-heads per kv group
    const int tid = threadIdx.x;
    const int tx = tid & 15;
    const int ty = tid >> 4;
    const int t0 = qt * 64;

    // load Q tile, prescaled by 1/sqrt(D) = 0.125
    const float* qbase = qkv + (((size_t)b * T_ + t0) * 48 + h) * 64;
    for (int r = tid >> 4; r < 64; r += 16) {
        float4 v = *(const float4*)(qbase + (size_t)r * F_ + (tid & 15) * 4);
        v.x *= 0.125f; v.y *= 0.125f; v.z *= 0.125f; v.w *= 0.125f;
        *(float4*)&Qs[r * 64 + (tid & 15) * 4] = v;
    }
    __syncthreads();

    float oacc[4][4];
    float m_i[4], l_i[4];
#pragma unroll
    for (int i = 0; i < 4; i++) {
        m_i[i] = -FLT_MAX;
        l_i[i] = 0.0f;
#pragma unroll
        for (int j = 0; j < 4; j++) oacc[i][j] = 0.0f;
    }

    const float* kbase = ck + (((size_t)b * S_) * G_ + g) * 64;
    const float* vbase = cv + (((size_t)b * S_) * G_ + g) * 64;

    for (int scn = 0; scn <= qt; scn++) {
        // load K chunk -> KV
        {
            const float* kb = kbase + (size_t)scn * 64 * (G_ * 64);
            for (int r = tid >> 4; r < 64; r += 16) {
                float4 v = *(const float4*)(kb + (size_t)r * (G_ * 64) + (tid & 15) * 4);
                *(float4*)&KV[r * KVROW + (tid & 15) * 4] = v;
            }
        }
        __syncthreads();

        // scores: sc[i][j] = Q[row] . K[col]
        float sc[4][4];
#pragma unroll
        for (int i = 0; i < 4; i++)
#pragma unroll
            for (int j = 0; j < 4; j++) sc[i][j] = 0.0f;

#pragma unroll
        for (int d4 = 0; d4 < 64; d4 += 4) {
            float4 q4[4], k4[4];
#pragma unroll
            for (int i = 0; i < 4; i++)
                q4[i] = *(const float4*)&Qs[(ty * 4 + i) * 64 + d4];
#pragma unroll
            for (int j = 0; j < 4; j++)
                k4[j] = *(const float4*)&KV[(tx * 4 + j) * KVROW + d4];
#pragma unroll
            for (int i = 0; i < 4; i++)
#pragma unroll
                for (int j = 0; j < 4; j++) {
                    sc[i][j] += q4[i].x * k4[j].x;
                    sc[i][j] += q4[i].y * k4[j].y;
                    sc[i][j] += q4[i].z * k4[j].z;
                    sc[i][j] += q4[i].w * k4[j].w;
                }
        }

        // mask only needed on the diagonal chunk (off-diag lower-tri is 0)
        if (scn == qt) {
#pragma unroll
            for (int i = 0; i < 4; i++) {
                const float* mrow =
                    mask + (size_t)(t0 + ty * 4 + i) * S_ + scn * 64 + tx * 4;
                float4 mv = *(const float4*)mrow;
                sc[i][0] += mv.x;
                sc[i][1] += mv.y;
                sc[i][2] += mv.z;
                sc[i][3] += mv.w;
            }
        }

        // online softmax (row groups = 16 lanes sharing ty)
#pragma unroll
        for (int i = 0; i < 4; i++) {
            float cm = fmaxf(fmaxf(sc[i][0], sc[i][1]), fmaxf(sc[i][2], sc[i][3]));
#pragma unroll
            for (int off = 8; off >= 1; off >>= 1)
                cm = fmaxf(cm, __shfl_xor_sync(0xffffffffu, cm, off));
            float mnew = fmaxf(m_i[i], cm);
            float alpha = __expf(m_i[i] - mnew);
            float rs = 0.0f;
#pragma unroll
            for (int j = 0; j < 4; j++) {
                sc[i][j] = __expf(sc[i][j] - mnew);
                rs += sc[i][j];
            }
#pragma unroll
            for (int off = 8; off >= 1; off >>= 1)
                rs += __shfl_xor_sync(0xffffffffu, rs, off);
            l_i[i] = l_i[i] * alpha + rs;
            m_i[i] = mnew;
#pragma unroll
            for (int j = 0; j < 4; j++) oacc[i][j] *= alpha;
        }
        __syncthreads();  // all K reads done

        // store P, load V into KV
#pragma unroll
        for (int i = 0; i < 4; i++)
            *(float4*)&Ps[(ty * 4 + i) * 64 + tx * 4] =
                make_float4(sc[i][0], sc[i][1], sc[i][2], sc[i][3]);
        {
            const float* vb = vbase + (size_t)scn * 64 * (G_ * 64);
            for (int r = tid >> 4; r < 64; r += 16) {
                float4 v = *(const float4*)(vb + (size_t)r * (G_ * 64) + (tid & 15) * 4);
                *(float4*)&KV[r * KVROW + (tid & 15) * 4] = v;
            }
        }
        __syncthreads();

        // O += P @ V
#pragma unroll 4
        for (int s = 0; s < 64; s++) {
            float4 v4 = *(const float4*)&KV[s * KVROW + tx * 4];
#pragma unroll
            for (int i = 0; i < 4; i++) {
                float p = Ps[(ty * 4 + i) * 64 + s];
                oacc[i][0] += p * v4.x;
                oacc[i][1] += p * v4.y;
                oacc[i][2] += p * v4.z;
                oacc[i][3] += p * v4.w;
            }
        }
        __syncthreads();  // KV/Ps free for next chunk
    }

    // epilogue: normalize, write o[b, t, h*64 + c]
#pragma unroll
    for (int i = 0; i < 4; i++) {
        float inv = 1.0f / l_i[i];
        int t = t0 + ty * 4 + i;
        float4 val = make_float4(oacc[i][0] * inv, oacc[i][1] * inv,
                                 oacc[i][2] * inv, oacc[i][3] * inv);
        *(float4*)&o[(((size_t)b * T_ + t) * H_ + h) * 64 + tx * 4] = val;
    }
}

// ---------------- launcher ----------------
extern "C" void kernel_launch(void* const* d_in, const int* in_sizes, int n_in,
                              void* d_out, int out_size) {
    const float* x = (const float*)d_in[0];
    const float* Wqkv = (const float*)d_in[1];
    const float* Wout = (const float*)d_in[2];
    const float* qw = (const float*)d_in[3];
    const float* kw = (const float*)d_in[4];
    const float* cosb = (const float*)d_in[5];
    const float* sinb = (const float*)d_in[6];
    const float* mask = (const float*)d_in[7];
    const float* ck_in = (const float*)d_in[8];
    const float* cv_in = (const float*)d_in[9];
    const int* pos = (const int*)d_in[10];

    float* y = (float*)d_out;
    float* ck = y + (size_t)B_ * T_ * E_;
    float* cv = ck + (size_t)B_ * S_ * G_ * D_;

    void* pq = nullptr;
    void* po = nullptr;
    cudaGetSymbolAddress(&pq, g_qkv);
    cudaGetSymbolAddress(&po, g_o);
    float* qkvbuf = (float*)pq;
    float* obuf = (float*)po;

    const size_t cacheBytes = sizeof(float) * (size_t)B_ * S_ * G_ * D_;
    cudaMemcpyAsync(ck, ck_in, cacheBytes, cudaMemcpyDeviceToDevice, 0);
    cudaMemcpyAsync(cv, cv_in, cacheBytes, cudaMemcpyDeviceToDevice, 0);

    // 1) QKV projection: (4096 x 2048) * (3072 x 2048)^T
    sgemm_nt<<<dim3(F_ / 128, (B_ * T_) / 128), 256>>>(x, Wqkv, qkvbuf,
                                                       B_ * T_, F_, E_);

    // 2) rmsnorm + rope + cache scatter
    rmsrope_kernel<<<B_ * T_, 256>>>(qkvbuf, qw, kw, cosb, sinb, pos, ck, cv);

    // 3) attention
    cudaFuncSetAttribute(attn_kernel, cudaFuncAttributeMaxDynamicSharedMemorySize,
                         50176);
    attn_kernel<<<dim3(T_ / 64, H_, B_), 256, 50176>>>(qkvbuf, ck, cv, mask, obuf);

    // 4) output projection: (4096 x 2048) * (2048 x 2048)^T
    sgemm_nt<<<dim3(E_ / 128, (B_ * T_) / 128), 256>>>(obuf, Wout, y,
                                                       B_ * T_, E_, E_);
}

// round 2
// speedup vs baseline: 1.4817x; 1.4817x over previous
#include <cuda_runtime.h>
#include <math.h>
#include <float.h>

#define B_ 2
#define T_ 2048
#define E_ 2048
#define H_ 32
#define G_ 8
#define D_ 64
#define S_ 2048
#define F_ 3072            // (H + 2G) * D
#define EPSV 1e-6f

// ---------------- scratch (device globals: allocation-free) ----------------
__device__ float g_qkv[(size_t)B_ * T_ * F_];        // 4096 x 3072
__device__ float g_o[(size_t)B_ * T_ * H_ * D_];     // 4096 x 2048

// ---------------- helpers ----------------
__device__ __forceinline__ unsigned f2tf(float f) {
    unsigned r;
    asm("cvt.rna.tf32.f32 %0, %1;" : "=r"(r) : "f"(f));
    return r;
}

__device__ __forceinline__ void mma_tf32(float* c, const unsigned* a,
                                         const unsigned* b) {
    asm volatile(
        "mma.sync.aligned.m16n8k8.row.col.f32.tf32.tf32.f32 "
        "{%0,%1,%2,%3}, {%4,%5,%6,%7}, {%8,%9}, {%0,%1,%2,%3};"
        : "+f"(c[0]), "+f"(c[1]), "+f"(c[2]), "+f"(c[3])
        : "r"(a[0]), "r"(a[1]), "r"(a[2]), "r"(a[3]), "r"(b[0]), "r"(b[1]));
}

// ---------------- TF32 tensor-core GEMM: C(MxN) = A(MxK) * B(NxK)^T -------
// 128x128x16 block tile, 256 threads = 8 warps (2x4), 64x32 warp tile.
#define ASTRIDE 136
__global__ __launch_bounds__(256) void gemm_tf32(const float* __restrict__ A,
                                                 const float* __restrict__ B,
                                                 float* __restrict__ C,
                                                 int M, int N, int K) {
    __shared__ unsigned As[16][ASTRIDE];
    __shared__ unsigned Bs[16][ASTRIDE];

    const int tid = threadIdx.x;
    const int lane = tid & 31;
    const int wid = tid >> 5;
    const int qid = lane >> 2;   // 0..7
    const int tig = lane & 3;    // 0..3
    const int warpM = wid & 1;   // 0..1
    const int warpN = wid >> 1;  // 0..3
    const int mW = warpM * 64;
    const int nW = warpN * 32;

    const int mBase = blockIdx.y * 128;
    const int nBase = blockIdx.x * 128;

    const int lrow = tid >> 1;           // 0..127
    const int lk = (tid & 1) * 8;        // 0 or 8
    const float* Ap = A + (size_t)(mBase + lrow) * K + lk;
    const float* Bp = B + (size_t)(nBase + lrow) * K + lk;

    float acc[4][4][4];
#pragma unroll
    for (int i = 0; i < 4; i++)
#pragma unroll
        for (int j = 0; j < 4; j++)
#pragma unroll
            for (int r = 0; r < 4; r++) acc[i][j][r] = 0.0f;

    // preload tile 0
    {
        float4 a0 = *(const float4*)(Ap + 0);
        float4 a1 = *(const float4*)(Ap + 4);
        float4 b0 = *(const float4*)(Bp + 0);
        float4 b1 = *(const float4*)(Bp + 4);
        As[lk + 0][lrow] = f2tf(a0.x); As[lk + 1][lrow] = f2tf(a0.y);
        As[lk + 2][lrow] = f2tf(a0.z); As[lk + 3][lrow] = f2tf(a0.w);
        As[lk + 4][lrow] = f2tf(a1.x); As[lk + 5][lrow] = f2tf(a1.y);
        As[lk + 6][lrow] = f2tf(a1.z); As[lk + 7][lrow] = f2tf(a1.w);
        Bs[lk + 0][lrow] = f2tf(b0.x); Bs[lk + 1][lrow] = f2tf(b0.y);
        Bs[lk + 2][lrow] = f2tf(b0.z); Bs[lk + 3][lrow] = f2tf(b0.w);
        Bs[lk + 4][lrow] = f2tf(b1.x); Bs[lk + 5][lrow] = f2tf(b1.y);
        Bs[lk + 6][lrow] = f2tf(b1.z); Bs[lk + 7][lrow] = f2tf(b1.w);
    }
    __syncthreads();

    for (int k0 = 0; k0 < K; k0 += 16) {
        // prefetch next tile into registers
        float4 na0, na1, nb0, nb1;
        const bool more = (k0 + 16) < K;
        if (more) {
            na0 = *(const float4*)(Ap + k0 + 16);
            na1 = *(const float4*)(Ap + k0 + 20);
            nb0 = *(const float4*)(Bp + k0 + 16);
            nb1 = *(const float4*)(Bp + k0 + 20);
        }

        // compute on current smem tile
#pragma unroll
        for (int ks = 0; ks < 16; ks += 8) {
            unsigned af[4][4], bf[4][2];
            const int kf = ks + tig;
#pragma unroll
            for (int mt = 0; mt < 4; mt++) {
                const int r = mW + mt * 16 + qid;
                af[mt][0] = As[kf][r];
                af[mt][1] = As[kf][r + 8];
                af[mt][2] = As[kf + 4][r];
                af[mt][3] = As[kf + 4][r + 8];
            }
#pragma unroll
            for (int nt = 0; nt < 4; nt++) {
                const int cc = nW + nt * 8 + qid;
                bf[nt][0] = Bs[kf][cc];
                bf[nt][1] = Bs[kf + 4][cc];
            }
#pragma unroll
            for (int mt = 0; mt < 4; mt++)
#pragma unroll
                for (int nt = 0; nt < 4; nt++)
                    mma_tf32(acc[mt][nt], af[mt], bf[nt]);
        }
        __syncthreads();
        if (more) {
            As[lk + 0][lrow] = f2tf(na0.x); As[lk + 1][lrow] = f2tf(na0.y);
            As[lk + 2][lrow] = f2tf(na0.z); As[lk + 3][lrow] = f2tf(na0.w);
            As[lk + 4][lrow] = f2tf(na1.x); As[lk + 5][lrow] = f2tf(na1.y);
            As[lk + 6][lrow] = f2tf(na1.z); As[lk + 7][lrow] = f2tf(na1.w);
            Bs[lk + 0][lrow] = f2tf(nb0.x); Bs[lk + 1][lrow] = f2tf(nb0.y);
            Bs[lk + 2][lrow] = f2tf(nb0.z); Bs[lk + 3][lrow] = f2tf(nb0.w);
            Bs[lk + 4][lrow] = f2tf(nb1.x); Bs[lk + 5][lrow] = f2tf(nb1.y);
            Bs[lk + 6][lrow] = f2tf(nb1.z); Bs[lk + 7][lrow] = f2tf(nb1.w);
            __syncthreads();
        }
    }

    // epilogue
#pragma unroll
    for (int mt = 0; mt < 4; mt++) {
#pragma unroll
        for (int nt = 0; nt < 4; nt++) {
            const int row = mBase + mW + mt * 16 + qid;
            const int col = nBase + nW + nt * 8 + tig * 2;
            *(float2*)&C[(size_t)row * N + col] =
                make_float2(acc[mt][nt][0], acc[mt][nt][1]);
            *(float2*)&C[(size_t)(row + 8) * N + col] =
                make_float2(acc[mt][nt][2], acc[mt][nt][3]);
        }
    }
}

// ---------------- RMSNorm + RoPE + cache scatter ----------------
__global__ __launch_bounds__(256) void rmsrope_kernel(
    float* __restrict__ qkv, const float* __restrict__ qw,
    const float* __restrict__ kw, const float* __restrict__ cosb,
    const float* __restrict__ sinb, const int* __restrict__ pos,
    float* __restrict__ ck, float* __restrict__ cv) {
    const int bt = blockIdx.x;
    const int b = bt / T_;
    const int t = bt % T_;
    const int lane = threadIdx.x & 31;
    const int w = threadIdx.x >> 5;
    const int p = pos[t];
    const float c = cosb[t * 32 + lane];
    const float s = sinb[t * 32 + lane];
    float* base = qkv + (size_t)bt * F_;

    for (int hh = w; hh < 48; hh += 8) {
        float* v = base + hh * 64;
        float x1 = v[lane];
        float x2 = v[lane + 32];
        if (hh < 40) {
            float ss = x1 * x1 + x2 * x2;
#pragma unroll
            for (int off = 16; off >= 1; off >>= 1)
                ss += __shfl_xor_sync(0xffffffffu, ss, off);
            float inv = rsqrtf(ss * (1.0f / 64.0f) + EPSV);
            const float* wgt = (hh < 32) ? qw : kw;
            float n1 = x1 * inv * wgt[lane];
            float n2 = x2 * inv * wgt[lane + 32];
            float r1 = n1 * c - n2 * s;
            float r2 = n2 * c + n1 * s;
            if (hh < 32) {
                v[lane] = r1;
                v[lane + 32] = r2;
            } else {
                float* dst = ck + (((size_t)b * S_ + p) * G_ + (hh - 32)) * 64;
                dst[lane] = r1;
                dst[lane + 32] = r2;
            }
        } else {
            float* dst = cv + (((size_t)b * S_ + p) * G_ + (hh - 40)) * 64;
            dst[lane] = x1;
            dst[lane + 32] = x2;
        }
    }
}

// ---------------- Flash attention (fp32) ----------------
#define KVROW 68
__global__ __launch_bounds__(256) void attn_kernel(
    const float* __restrict__ qkv, const float* __restrict__ ck,
    const float* __restrict__ cv, const float* __restrict__ mask,
    float* __restrict__ o) {
    extern __shared__ float sm[];
    float* Qs = sm;                 // [64][64]
    float* KV = sm + 64 * 64;       // [64][68]
    float* Ps = KV + 64 * KVROW;    // [64][64]

    const int qt = blockIdx.x;
    const int h = blockIdx.y;
    const int b = blockIdx.z;
    const int g = h >> 2;
    const int tid = threadIdx.x;
    const int tx = tid & 15;
    const int ty = tid >> 4;
    const int t0 = qt * 64;

    const float* qbase = qkv + (((size_t)b * T_ + t0) * 48 + h) * 64;
    for (int r = tid >> 4; r < 64; r += 16) {
        float4 v = *(const float4*)(qbase + (size_t)r * F_ + (tid & 15) * 4);
        v.x *= 0.125f; v.y *= 0.125f; v.z *= 0.125f; v.w *= 0.125f;
        *(float4*)&Qs[r * 64 + (tid & 15) * 4] = v;
    }
    __syncthreads();

    float oacc[4][4];
    float m_i[4], l_i[4];
#pragma unroll
    for (int i = 0; i < 4; i++) {
        m_i[i] = -FLT_MAX;
        l_i[i] = 0.0f;
#pragma unroll
        for (int j = 0; j < 4; j++) oacc[i][j] = 0.0f;
    }

    const float* kbase = ck + (((size_t)b * S_) * G_ + g) * 64;
    const float* vbase = cv + (((size_t)b * S_) * G_ + g) * 64;

    for (int scn = 0; scn <= qt; scn++) {
        {
            const float* kb = kbase + (size_t)scn * 64 * (G_ * 64);
            for (int r = tid >> 4; r < 64; r += 16) {
                float4 v = *(const float4*)(kb + (size_t)r * (G_ * 64) + (tid & 15) * 4);
                *(float4*)&KV[r * KVROW + (tid & 15) * 4] = v;
            }
        }
        __syncthreads();

        float sc[4][4];
#pragma unroll
        for (int i = 0; i < 4; i++)
#pragma unroll
            for (int j = 0; j < 4; j++) sc[i][j] = 0.0f;

#pragma unroll
        for (int d4 = 0; d4 < 64; d4 += 4) {
            float4 q4[4], k4[4];
#pragma unroll
            for (int i = 0; i < 4; i++)
                q4[i] = *(const float4*)&Qs[(ty * 4 + i) * 64 + d4];
#pragma unroll
            for (int j = 0; j < 4; j++)
                k4[j] = *(const float4*)&KV[(tx * 4 + j) * KVROW + d4];
#pragma unroll
            for (int i = 0; i < 4; i++)
#pragma unroll
                for (int j = 0; j < 4; j++) {
                    sc[i][j] += q4[i].x * k4[j].x;
                    sc[i][j] += q4[i].y * k4[j].y;
                    sc[i][j] += q4[i].z * k4[j].z;
                    sc[i][j] += q4[i].w * k4[j].w;
                }
        }

        if (scn == qt) {
#pragma unroll
            for (int i = 0; i < 4; i++) {
                const float* mrow =
                    mask + (size_t)(t0 + ty * 4 + i) * S_ + scn * 64 + tx * 4;
                float4 mv = *(const float4*)mrow;
                sc[i][0] += mv.x;
                sc[i][1] += mv.y;
                sc[i][2] += mv.z;
                sc[i][3] += mv.w;
            }
        }

#pragma unroll
        for (int i = 0; i < 4; i++) {
            float cm = fmaxf(fmaxf(sc[i][0], sc[i][1]), fmaxf(sc[i][2], sc[i][3]));
#pragma unroll
            for (int off = 8; off >= 1; off >>= 1)
                cm = fmaxf(cm, __shfl_xor_sync(0xffffffffu, cm, off));
            float mnew = fmaxf(m_i[i], cm);
            float alpha = __expf(m_i[i] - mnew);
            float rs = 0.0f;
#pragma unroll
            for (int j = 0; j < 4; j++) {
                sc[i][j] = __expf(sc[i][j] - mnew);
                rs += sc[i][j];
            }
#pragma unroll
            for (int off = 8; off >= 1; off >>= 1)
                rs += __shfl_xor_sync(0xffffffffu, rs, off);
            l_i[i] = l_i[i] * alpha + rs;
            m_i[i] = mnew;
#pragma unroll
            for (int j = 0; j < 4; j++) oacc[i][j] *= alpha;
        }
        __syncthreads();

#pragma unroll
        for (int i = 0; i < 4; i++)
            *(float4*)&Ps[(ty * 4 + i) * 64 + tx * 4] =
                make_float4(sc[i][0], sc[i][1], sc[i][2], sc[i][3]);
        {
            const float* vb = vbase + (size_t)scn * 64 * (G_ * 64);
            for (int r = tid >> 4; r < 64; r += 16) {
                float4 v = *(const float4*)(vb + (size_t)r * (G_ * 64) + (tid & 15) * 4);
                *(float4*)&KV[r * KVROW + (tid & 15) * 4] = v;
            }
        }
        __syncthreads();

#pragma unroll 4
        for (int s = 0; s < 64; s++) {
            float4 v4 = *(const float4*)&KV[s * KVROW + tx * 4];
#pragma unroll
            for (int i = 0; i < 4; i++) {
                float p = Ps[(ty * 4 + i) * 64 + s];
                oacc[i][0] += p * v4.x;
                oacc[i][1] += p * v4.y;
                oacc[i][2] += p * v4.z;
                oacc[i][3] += p * v4.w;
            }
        }
        __syncthreads();
    }

#pragma unroll
    for (int i = 0; i < 4; i++) {
        float inv = 1.0f / l_i[i];
        int t = t0 + ty * 4 + i;
        float4 val = make_float4(oacc[i][0] * inv, oacc[i][1] * inv,
                                 oacc[i][2] * inv, oacc[i][3] * inv);
        *(float4*)&o[(((size_t)b * T_ + t) * H_ + h) * 64 + tx * 4] = val;
    }
}

// ---------------- launcher ----------------
extern "C" void kernel_launch(void* const* d_in, const int* in_sizes, int n_in,
                              void* d_out, int out_size) {
    const float* x = (const float*)d_in[0];
    const float* Wqkv = (const float*)d_in[1];
    const float* Wout = (const float*)d_in[2];
    const float* qw = (const float*)d_in[3];
    const float* kw = (const float*)d_in[4];
    const float* cosb = (const float*)d_in[5];
    const float* sinb = (const float*)d_in[6];
    const float* mask = (const float*)d_in[7];
    const float* ck_in = (const float*)d_in[8];
    const float* cv_in = (const float*)d_in[9];
    const int* pos = (const int*)d_in[10];

    float* y = (float*)d_out;
    float* ck = y + (size_t)B_ * T_ * E_;
    float* cv = ck + (size_t)B_ * S_ * G_ * D_;

    void* pq = nullptr;
    void* po = nullptr;
    cudaGetSymbolAddress(&pq, g_qkv);
    cudaGetSymbolAddress(&po, g_o);
    float* qkvbuf = (float*)pq;
    float* obuf = (float*)po;

    const size_t cacheBytes = sizeof(float) * (size_t)B_ * S_ * G_ * D_;
    cudaMemcpyAsync(ck, ck_in, cacheBytes, cudaMemcpyDeviceToDevice, 0);
    cudaMemcpyAsync(cv, cv_in, cacheBytes, cudaMemcpyDeviceToDevice, 0);

    // 1) QKV projection: (4096 x 2048) * (3072 x 2048)^T
    gemm_tf32<<<dim3(F_ / 128, (B_ * T_) / 128), 256>>>(x, Wqkv, qkvbuf,
                                                        B_ * T_, F_, E_);

    // 2) rmsnorm + rope + cache scatter
    rmsrope_kernel<<<B_ * T_, 256>>>(qkvbuf, qw, kw, cosb, sinb, pos, ck, cv);

    // 3) attention
    cudaFuncSetAttribute(attn_kernel, cudaFuncAttributeMaxDynamicSharedMemorySize,
                         50176);
    attn_kernel<<<dim3(T_ / 64, H_, B_), 256, 50176>>>(qkvbuf, ck, cv, mask, obuf);

    // 4) output projection: (4096 x 2048) * (2048 x 2048)^T
    gemm_tf32<<<dim3(E_ / 128, (B_ * T_) / 128), 256>>>(obuf, Wout, y,
                                                        B_ * T_, E_, E_);
}

// round 3
// speedup vs baseline: 3.1151x; 2.1024x over previous
#include <cuda_runtime.h>
#include <math.h>
#include <float.h>

#define B_ 2
#define T_ 2048
#define E_ 2048
#define H_ 32
#define G_ 8
#define D_ 64
#define S_ 2048
#define F_ 3072            // (H + 2G) * D
#define EPSV 1e-6f

// ---------------- scratch (device globals: allocation-free) ----------------
__device__ float g_qkv[(size_t)B_ * T_ * F_];        // 4096 x 3072
__device__ float g_o[(size_t)B_ * T_ * H_ * D_];     // 4096 x 2048

// ---------------- helpers ----------------
__device__ __forceinline__ unsigned f2tf(float f) {
    unsigned r;
    asm("cvt.rna.tf32.f32 %0, %1;" : "=r"(r) : "f"(f));
    return r;
}

__device__ __forceinline__ void mma_tf32(float* c, const unsigned* a,
                                         const unsigned* b) {
    asm volatile(
        "mma.sync.aligned.m16n8k8.row.col.f32.tf32.tf32.f32 "
        "{%0,%1,%2,%3}, {%4,%5,%6,%7}, {%8,%9}, {%0,%1,%2,%3};"
        : "+f"(c[0]), "+f"(c[1]), "+f"(c[2]), "+f"(c[3])
        : "r"(a[0]), "r"(a[1]), "r"(a[2]), "r"(a[3]), "r"(b[0]), "r"(b[1]));
}

// ---------------- TF32 tensor-core GEMM: C(MxN) = A(MxK) * B(NxK)^T -------
#define ASTRIDE 136
__global__ __launch_bounds__(256) void gemm_tf32(const float* __restrict__ A,
                                                 const float* __restrict__ B,
                                                 float* __restrict__ C,
                                                 int M, int N, int K) {
    __shared__ unsigned As[16][ASTRIDE];
    __shared__ unsigned Bs[16][ASTRIDE];

    const int tid = threadIdx.x;
    const int lane = tid & 31;
    const int wid = tid >> 5;
    const int qid = lane >> 2;
    const int tig = lane & 3;
    const int warpM = wid & 1;
    const int warpN = wid >> 1;
    const int mW = warpM * 64;
    const int nW = warpN * 32;

    const int mBase = blockIdx.y * 128;
    const int nBase = blockIdx.x * 128;

    const int lrow = tid >> 1;
    const int lk = (tid & 1) * 8;
    const float* Ap = A + (size_t)(mBase + lrow) * K + lk;
    const float* Bp = B + (size_t)(nBase + lrow) * K + lk;

    float acc[4][4][4];
#pragma unroll
    for (int i = 0; i < 4; i++)
#pragma unroll
        for (int j = 0; j < 4; j++)
#pragma unroll
            for (int r = 0; r < 4; r++) acc[i][j][r] = 0.0f;

    {
        float4 a0 = *(const float4*)(Ap + 0);
        float4 a1 = *(const float4*)(Ap + 4);
        float4 b0 = *(const float4*)(Bp + 0);
        float4 b1 = *(const float4*)(Bp + 4);
        As[lk + 0][lrow] = f2tf(a0.x); As[lk + 1][lrow] = f2tf(a0.y);
        As[lk + 2][lrow] = f2tf(a0.z); As[lk + 3][lrow] = f2tf(a0.w);
        As[lk + 4][lrow] = f2tf(a1.x); As[lk + 5][lrow] = f2tf(a1.y);
        As[lk + 6][lrow] = f2tf(a1.z); As[lk + 7][lrow] = f2tf(a1.w);
        Bs[lk + 0][lrow] = f2tf(b0.x); Bs[lk + 1][lrow] = f2tf(b0.y);
        Bs[lk + 2][lrow] = f2tf(b0.z); Bs[lk + 3][lrow] = f2tf(b0.w);
        Bs[lk + 4][lrow] = f2tf(b1.x); Bs[lk + 5][lrow] = f2tf(b1.y);
        Bs[lk + 6][lrow] = f2tf(b1.z); Bs[lk + 7][lrow] = f2tf(b1.w);
    }
    __syncthreads();

    for (int k0 = 0; k0 < K; k0 += 16) {
        float4 na0, na1, nb0, nb1;
        const bool more = (k0 + 16) < K;
        if (more) {
            na0 = *(const float4*)(Ap + k0 + 16);
            na1 = *(const float4*)(Ap + k0 + 20);
            nb0 = *(const float4*)(Bp + k0 + 16);
            nb1 = *(const float4*)(Bp + k0 + 20);
        }

#pragma unroll
        for (int ks = 0; ks < 16; ks += 8) {
            unsigned af[4][4], bf[4][2];
            const int kf = ks + tig;
#pragma unroll
            for (int mt = 0; mt < 4; mt++) {
                const int r = mW + mt * 16 + qid;
                af[mt][0] = As[kf][r];
                af[mt][1] = As[kf][r + 8];
                af[mt][2] = As[kf + 4][r];
                af[mt][3] = As[kf + 4][r + 8];
            }
#pragma unroll
            for (int nt = 0; nt < 4; nt++) {
                const int cc = nW + nt * 8 + qid;
                bf[nt][0] = Bs[kf][cc];
                bf[nt][1] = Bs[kf + 4][cc];
            }
#pragma unroll
            for (int mt = 0; mt < 4; mt++)
#pragma unroll
                for (int nt = 0; nt < 4; nt++)
                    mma_tf32(acc[mt][nt], af[mt], bf[nt]);
        }
        __syncthreads();
        if (more) {
            As[lk + 0][lrow] = f2tf(na0.x); As[lk + 1][lrow] = f2tf(na0.y);
            As[lk + 2][lrow] = f2tf(na0.z); As[lk + 3][lrow] = f2tf(na0.w);
            As[lk + 4][lrow] = f2tf(na1.x); As[lk + 5][lrow] = f2tf(na1.y);
            As[lk + 6][lrow] = f2tf(na1.z); As[lk + 7][lrow] = f2tf(na1.w);
            Bs[lk + 0][lrow] = f2tf(nb0.x); Bs[lk + 1][lrow] = f2tf(nb0.y);
            Bs[lk + 2][lrow] = f2tf(nb0.z); Bs[lk + 3][lrow] = f2tf(nb0.w);
            Bs[lk + 4][lrow] = f2tf(nb1.x); Bs[lk + 5][lrow] = f2tf(nb1.y);
            Bs[lk + 6][lrow] = f2tf(nb1.z); Bs[lk + 7][lrow] = f2tf(nb1.w);
            __syncthreads();
        }
    }

#pragma unroll
    for (int mt = 0; mt < 4; mt++) {
#pragma unroll
        for (int nt = 0; nt < 4; nt++) {
            const int row = mBase + mW + mt * 16 + qid;
            const int col = nBase + nW + nt * 8 + tig * 2;
            *(float2*)&C[(size_t)row * N + col] =
                make_float2(acc[mt][nt][0], acc[mt][nt][1]);
            *(float2*)&C[(size_t)(row + 8) * N + col] =
                make_float2(acc[mt][nt][2], acc[mt][nt][3]);
        }
    }
}

// ---------------- RMSNorm + RoPE + cache scatter ----------------
__global__ __launch_bounds__(256) void rmsrope_kernel(
    float* __restrict__ qkv, const float* __restrict__ qw,
    const float* __restrict__ kw, const float* __restrict__ cosb,
    const float* __restrict__ sinb, const int* __restrict__ pos,
    float* __restrict__ ck, float* __restrict__ cv) {
    const int bt = blockIdx.x;
    const int b = bt / T_;
    const int t = bt % T_;
    const int lane = threadIdx.x & 31;
    const int w = threadIdx.x >> 5;
    const int p = pos[t];
    const float c = cosb[t * 32 + lane];
    const float s = sinb[t * 32 + lane];
    float* base = qkv + (size_t)bt * F_;

    for (int hh = w; hh < 48; hh += 8) {
        float* v = base + hh * 64;
        float x1 = v[lane];
        float x2 = v[lane + 32];
        if (hh < 40) {
            float ss = x1 * x1 + x2 * x2;
#pragma unroll
            for (int off = 16; off >= 1; off >>= 1)
                ss += __shfl_xor_sync(0xffffffffu, ss, off);
            float inv = rsqrtf(ss * (1.0f / 64.0f) + EPSV);
            const float* wgt = (hh < 32) ? qw : kw;
            float n1 = x1 * inv * wgt[lane];
            float n2 = x2 * inv * wgt[lane + 32];
            float r1 = n1 * c - n2 * s;
            float r2 = n2 * c + n1 * s;
            if (hh < 32) {
                v[lane] = r1;
                v[lane + 32] = r2;
            } else {
                float* dst = ck + (((size_t)b * S_ + p) * G_ + (hh - 32)) * 64;
                dst[lane] = r1;
                dst[lane + 32] = r2;
            }
        } else {
            float* dst = cv + (((size_t)b * S_ + p) * G_ + (hh - 40)) * 64;
            dst[lane] = x1;
            dst[lane + 32] = x2;
        }
    }
}

// ---------------- Tensor-core flash attention (tf32) ----------------
// grid (T/128, H, B), 256 threads = 8 warps; warp w owns q rows [w*16, w*16+16).
// Dynamic smem: Ks[64][68] + Vs[64][72] + Ps[128][68] (all tf32/unsigned).
#define KS_PAD 68
#define VS_PAD 72
#define PS_PAD 68
#define ATTN_SMEM ((64 * KS_PAD + 64 * VS_PAD + 128 * PS_PAD) * 4)

__global__ __launch_bounds__(256, 2) void attn_tc(
    const float* __restrict__ qkv, const float* __restrict__ ck,
    const float* __restrict__ cv, float* __restrict__ o) {
    extern __shared__ unsigned smu[];
    unsigned (*Ks)[KS_PAD] = (unsigned (*)[KS_PAD])smu;
    unsigned (*Vs)[VS_PAD] = (unsigned (*)[VS_PAD])(smu + 64 * KS_PAD);
    unsigned (*Ps)[PS_PAD] =
        (unsigned (*)[PS_PAD])(smu + 64 * KS_PAD + 64 * VS_PAD);

    const int bx = blockIdx.x;
    const int h = blockIdx.y;
    const int b = blockIdx.z;
    const int g = h >> 2;
    const int tid = threadIdx.x;
    const int lane = tid & 31;
    const int wid = tid >> 5;
    const int qid = lane >> 2;
    const int tig = lane & 3;
    const int t0 = bx * 128;
    const int wq = wid * 16;
    const int row0 = t0 + wq + qid;   // first abs q row of this thread
    const int row1 = row0 + 8;

    // Q fragments in registers (scaled by 1/sqrt(D))
    unsigned qa[8][4];
    {
        const float* q0 = qkv + (size_t)(b * T_ + row0) * F_ + h * 64;
        const float* q1 = q0 + (size_t)8 * F_;
#pragma unroll
        for (int s = 0; s < 8; s++) {
            qa[s][0] = f2tf(0.125f * q0[8 * s + tig]);
            qa[s][1] = f2tf(0.125f * q1[8 * s + tig]);
            qa[s][2] = f2tf(0.125f * q0[8 * s + tig + 4]);
            qa[s][3] = f2tf(0.125f * q1[8 * s + tig + 4]);
        }
    }

    float oacc[8][4];
#pragma unroll
    for (int nt = 0; nt < 8; nt++)
#pragma unroll
        for (int j = 0; j < 4; j++) oacc[nt][j] = 0.0f;
    float m0 = -FLT_MAX, m1 = -FLT_MAX, l0 = 0.0f, l1 = 0.0f;

    const float* kb = ck + ((size_t)b * S_ * G_ + g) * 64;
    const float* vb = cv + ((size_t)b * S_ * G_ + g) * 64;
    const int nch = 2 * bx + 2;

    for (int scn = 0; scn < nch; scn++) {
        __syncthreads();  // previous chunk's K/V reads complete
        {
            const float* kc = kb + (size_t)scn * 64 * (G_ * 64);
            const float* vc = vb + (size_t)scn * 64 * (G_ * 64);
            const int r = tid >> 4;
            const int c4 = (tid & 15) * 4;
#pragma unroll
            for (int rr = 0; rr < 4; rr++) {
                const int row = r + rr * 16;
                float4 k4 = *(const float4*)(kc + (size_t)row * (G_ * 64) + c4);
                float4 v4 = *(const float4*)(vc + (size_t)row * (G_ * 64) + c4);
                *(uint4*)&Ks[row][c4] =
                    make_uint4(f2tf(k4.x), f2tf(k4.y), f2tf(k4.z), f2tf(k4.w));
                *(uint4*)&Vs[row][c4] =
                    make_uint4(f2tf(v4.x), f2tf(v4.y), f2tf(v4.z), f2tf(v4.w));
            }
        }
        __syncthreads();

        if (scn * 64 <= t0 + wq + 15) {  // warp has at least one unmasked key
            float sc[8][4];
#pragma unroll
            for (int nt = 0; nt < 8; nt++)
#pragma unroll
                for (int j = 0; j < 4; j++) sc[nt][j] = 0.0f;

#pragma unroll
            for (int s = 0; s < 8; s++) {
#pragma unroll
                for (int nt = 0; nt < 8; nt++) {
                    unsigned bf[2];
                    bf[0] = Ks[nt * 8 + qid][8 * s + tig];
                    bf[1] = Ks[nt * 8 + qid][8 * s + tig + 4];
                    mma_tf32(sc[nt], qa[s], bf);
                }
            }

            // analytic causal mask (only boundary chunks need it)
            if (scn * 64 + 63 > t0 + wq) {
#pragma unroll
                for (int nt = 0; nt < 8; nt++) {
                    const int key0 = scn * 64 + nt * 8 + 2 * tig;
                    if (key0 > row0) sc[nt][0] = -1e30f;
                    if (key0 + 1 > row0) sc[nt][1] = -1e30f;
                    if (key0 > row1) sc[nt][2] = -1e30f;
                    if (key0 + 1 > row1) sc[nt][3] = -1e30f;
                }
            }

            // online softmax (rows: qid, qid+8; reduce across tig quad lanes)
            float cm0 = -FLT_MAX, cm1 = -FLT_MAX;
#pragma unroll
            for (int nt = 0; nt < 8; nt++) {
                cm0 = fmaxf(cm0, fmaxf(sc[nt][0], sc[nt][1]));
                cm1 = fmaxf(cm1, fmaxf(sc[nt][2], sc[nt][3]));
            }
            cm0 = fmaxf(cm0, __shfl_xor_sync(0xffffffffu, cm0, 1));
            cm0 = fmaxf(cm0, __shfl_xor_sync(0xffffffffu, cm0, 2));
            cm1 = fmaxf(cm1, __shfl_xor_sync(0xffffffffu, cm1, 1));
            cm1 = fmaxf(cm1, __shfl_xor_sync(0xffffffffu, cm1, 2));
            const float mn0 = fmaxf(m0, cm0);
            const float mn1 = fmaxf(m1, cm1);
            const float a0 = __expf(m0 - mn0);
            const float a1 = __expf(m1 - mn1);
            float rs0 = 0.0f, rs1 = 0.0f;
#pragma unroll
            for (int nt = 0; nt < 8; nt++) {
                sc[nt][0] = __expf(sc[nt][0] - mn0);
                sc[nt][1] = __expf(sc[nt][1] - mn0);
                sc[nt][2] = __expf(sc[nt][2] - mn1);
                sc[nt][3] = __expf(sc[nt][3] - mn1);
                rs0 += sc[nt][0] + sc[nt][1];
                rs1 += sc[nt][2] + sc[nt][3];
            }
            rs0 += __shfl_xor_sync(0xffffffffu, rs0, 1);
            rs0 += __shfl_xor_sync(0xffffffffu, rs0, 2);
            rs1 += __shfl_xor_sync(0xffffffffu, rs1, 1);
            rs1 += __shfl_xor_sync(0xffffffffu, rs1, 2);
            l0 = l0 * a0 + rs0;
            l1 = l1 * a1 + rs1;
            m0 = mn0;
            m1 = mn1;
#pragma unroll
            for (int nt = 0; nt < 8; nt++) {
                oacc[nt][0] *= a0;
                oacc[nt][1] *= a0;
                oacc[nt][2] *= a1;
                oacc[nt][3] *= a1;
            }

            // store P tile (warp-private rows) as tf32
#pragma unroll
            for (int nt = 0; nt < 8; nt++) {
                *(uint2*)&Ps[wq + qid][8 * nt + 2 * tig] =
                    make_uint2(f2tf(sc[nt][0]), f2tf(sc[nt][1]));
                *(uint2*)&Ps[wq + qid + 8][8 * nt + 2 * tig] =
                    make_uint2(f2tf(sc[nt][2]), f2tf(sc[nt][3]));
            }
            __syncwarp();

            // O += P @ V
#pragma unroll
            for (int s = 0; s < 8; s++) {
                unsigned pa[4];
                pa[0] = Ps[wq + qid][8 * s + tig];
                pa[1] = Ps[wq + qid + 8][8 * s + tig];
                pa[2] = Ps[wq + qid][8 * s + tig + 4];
                pa[3] = Ps[wq + qid + 8][8 * s + tig + 4];
#pragma unroll
                for (int nt = 0; nt < 8; nt++) {
                    unsigned vf[2];
                    vf[0] = Vs[8 * s + tig][8 * nt + qid];
                    vf[1] = Vs[8 * s + tig + 4][8 * nt + qid];
                    mma_tf32(oacc[nt], pa, vf);
                }
            }
        }
    }

    // epilogue
    const float i0 = 1.0f / l0;
    const float i1 = 1.0f / l1;
#pragma unroll
    for (int nt = 0; nt < 8; nt++) {
        const int col = h * 64 + 8 * nt + 2 * tig;
        *(float2*)&o[(size_t)(b * T_ + row0) * (H_ * D_) + col] =
            make_float2(oacc[nt][0] * i0, oacc[nt][1] * i0);
        *(float2*)&o[(size_t)(b * T_ + row1) * (H_ * D_) + col] =
            make_float2(oacc[nt][2] * i1, oacc[nt][3] * i1);
    }
}

// ---------------- launcher ----------------
extern "C" void kernel_launch(void* const* d_in, const int* in_sizes, int n_in,
                              void* d_out, int out_size) {
    const float* x = (const float*)d_in[0];
    const float* Wqkv = (const float*)d_in[1];
    const float* Wout = (const float*)d_in[2];
    const float* qw = (const float*)d_in[3];
    const float* kw = (const float*)d_in[4];
    const float* cosb = (const float*)d_in[5];
    const float* sinb = (const float*)d_in[6];
    const int* pos = (const int*)d_in[10];

    float* y = (float*)d_out;
    float* ck = y + (size_t)B_ * T_ * E_;
    float* cv = ck + (size_t)B_ * S_ * G_ * D_;

    void* pq = nullptr;
    void* po = nullptr;
    cudaGetSymbolAddress(&pq, g_qkv);
    cudaGetSymbolAddress(&po, g_o);
    float* qkvbuf = (float*)pq;
    float* obuf = (float*)po;

    const size_t cacheBytes = sizeof(float) * (size_t)B_ * S_ * G_ * D_;
    cudaMemcpyAsync(ck, (const float*)d_in[8], cacheBytes,
                    cudaMemcpyDeviceToDevice, 0);
    cudaMemcpyAsync(cv, (const float*)d_in[9], cacheBytes,
                    cudaMemcpyDeviceToDevice, 0);

    // 1) QKV projection
    gemm_tf32<<<dim3(F_ / 128, (B_ * T_) / 128), 256>>>(x, Wqkv, qkvbuf,
                                                        B_ * T_, F_, E_);

    // 2) rmsnorm + rope + cache scatter
    rmsrope_kernel<<<B_ * T_, 256>>>(qkvbuf, qw, kw, cosb, sinb, pos, ck, cv);

    // 3) tensor-core attention
    static int attn_cfg = 0;
    if (!attn_cfg) {
        cudaFuncSetAttribute(attn_tc, cudaFuncAttributeMaxDynamicSharedMemorySize,
                             ATTN_SMEM);
        attn_cfg = 1;
    }
    attn_tc<<<dim3(T_ / 128, H_, B_), 256, ATTN_SMEM>>>(qkvbuf, ck, cv, obuf);

    // 4) output projection
    gemm_tf32<<<dim3(E_ / 128, (B_ * T_) / 128), 256>>>(obuf, Wout, y,
                                                        B_ * T_, E_, E_);
}

// round 5
// speedup vs baseline: 4.4757x; 1.4368x over previous
#include <cuda_runtime.h>
#include <math.h>
#include <float.h>
#include <stdint.h>

#define B_ 2
#define T_ 2048
#define E_ 2048
#define H_ 32
#define G_ 8
#define D_ 64
#define S_ 2048
#define F_ 3072            // (H + 2G) * D
#define EPSV 1e-6f

// ---------------- scratch (device globals: allocation-free) ----------------
__device__ float g_qkv[(size_t)B_ * T_ * F_];        // 4096 x 3072
__device__ float g_o[(size_t)B_ * T_ * H_ * D_];     // 4096 x 2048

// ---------------- helpers ----------------
__device__ __forceinline__ unsigned f2tf(float f) {
    unsigned r;
    asm("cvt.rna.tf32.f32 %0, %1;" : "=r"(r) : "f"(f));
    return r;
}

__device__ __forceinline__ void mma_tf32(float* c, const unsigned* a,
                                         const unsigned* b) {
    asm volatile(
        "mma.sync.aligned.m16n8k8.row.col.f32.tf32.tf32.f32 "
        "{%0,%1,%2,%3}, {%4,%5,%6,%7}, {%8,%9}, {%0,%1,%2,%3};"
        : "+f"(c[0]), "+f"(c[1]), "+f"(c[2]), "+f"(c[3])
        : "r"(a[0]), "r"(a[1]), "r"(a[2]), "r"(a[3]), "r"(b[0]), "r"(b[1]));
}

__device__ __forceinline__ uint32_t smem_u32(const void* p) {
    uint32_t a;
    asm("{ .reg .u64 t; cvta.to.shared.u64 t, %1; cvt.u32.u64 %0, t; }"
        : "=r"(a) : "l"(p));
    return a;
}

__device__ __forceinline__ void cp16(uint32_t dst, const void* src) {
    asm volatile("cp.async.cg.shared.global [%0], [%1], 16;" ::"r"(dst),
                 "l"(src));
}

// ---------------- cp.async-pipelined TF32 GEMM -----------------------------
// C(MxN) = A(MxK) * B(NxK)^T, row-major. 128x128 tile, BK=32, 3 stages.
// 256 threads = 8 warps (2x4), warp tile 64x32, m16n8k8 tf32 MMAs.
#define BK 32
#define AST 36                           // floats per smem row (pad 4)
#define STG_FLOATS (128 * AST)           // 4608 floats = 18432 B per matrix
#define GM_STAGES 3
#define GM_SMEM (GM_STAGES * 2 * STG_FLOATS * 4)  // 110592 B

__device__ __forceinline__ void load_stage(const float* gA, const float* gB,
                                           uint32_t smA, uint32_t smB, int K,
                                           int tid) {
#pragma unroll
    for (int o = 0; o < 4; o++) {
        const int ci = o * 256 + tid;    // 0..1023, 16B chunks
        const int r = ci >> 3;
        const int c = ci & 7;
        const uint32_t soff = (uint32_t)(r * AST + c * 4) * 4u;
        cp16(smA + soff, gA + (size_t)r * K + c * 4);
        cp16(smB + soff, gB + (size_t)r * K + c * 4);
    }
}

__global__ __launch_bounds__(256, 2) void gemm_cp(const float* __restrict__ A,
                                                  const float* __restrict__ B,
                                                  float* __restrict__ C,
                                                  int M, int N, int K) {
    extern __shared__ float sm[];
    const uint32_t smb = smem_u32(sm);
    const int tid = threadIdx.x;
    const int lane = tid & 31;
    const int wid = tid >> 5;
    const int qid = lane >> 2;
    const int tig = lane & 3;
    const int mW = (wid & 1) * 64;
    const int nW = (wid >> 1) * 32;
    const int mBase = blockIdx.y * 128;
    const int nBase = blockIdx.x * 128;

    const float* Ab = A + (size_t)mBase * K;
    const float* Bb = B + (size_t)nBase * K;

    float acc[4][4][4];
#pragma unroll
    for (int i = 0; i < 4; i++)
#pragma unroll
        for (int j = 0; j < 4; j++)
#pragma unroll
            for (int r = 0; r < 4; r++) acc[i][j][r] = 0.0f;

    const int nch = K / BK;

#pragma unroll
    for (int s = 0; s < GM_STAGES; s++) {
        const uint32_t base = smb + (uint32_t)s * 2u * STG_FLOATS * 4u;
        load_stage(Ab + s * BK, Bb + s * BK, base, base + STG_FLOATS * 4u, K,
                   tid);
        asm volatile("cp.async.commit_group;");
    }

    for (int i = 0; i < nch; i++) {
        const int s = i % GM_STAGES;
        const float* As = sm + (size_t)s * 2 * STG_FLOATS;
        const float* Bs = As + STG_FLOATS;

        asm volatile("cp.async.wait_group 2;");
        __syncthreads();

#pragma unroll
        for (int ks = 0; ks < 4; ks++) {
            const int kf = ks * 8 + tig;
            unsigned af[4][4], bf[4][2];
#pragma unroll
            for (int mt = 0; mt < 4; mt++) {
                const int r = mW + mt * 16 + qid;
                af[mt][0] = f2tf(As[r * AST + kf]);
                af[mt][1] = f2tf(As[(r + 8) * AST + kf]);
                af[mt][2] = f2tf(As[r * AST + kf + 4]);
                af[mt][3] = f2tf(As[(r + 8) * AST + kf + 4]);
            }
#pragma unroll
            for (int nt = 0; nt < 4; nt++) {
                const int cc = nW + nt * 8 + qid;
                bf[nt][0] = f2tf(Bs[cc * AST + kf]);
                bf[nt][1] = f2tf(Bs[cc * AST + kf + 4]);
            }
#pragma unroll
            for (int mt = 0; mt < 4; mt++)
#pragma unroll
                for (int nt = 0; nt < 4; nt++)
                    mma_tf32(acc[mt][nt], af[mt], bf[nt]);
        }
        __syncthreads();

        if (i + GM_STAGES < nch) {
            const uint32_t base = smb + (uint32_t)s * 2u * STG_FLOATS * 4u;
            load_stage(Ab + (size_t)(i + GM_STAGES) * BK,
                       Bb + (size_t)(i + GM_STAGES) * BK, base,
                       base + STG_FLOATS * 4u, K, tid);
        }
        asm volatile("cp.async.commit_group;");
    }

#pragma unroll
    for (int mt = 0; mt < 4; mt++) {
#pragma unroll
        for (int nt = 0; nt < 4; nt++) {
            const int row = mBase + mW + mt * 16 + qid;
            const int col = nBase + nW + nt * 8 + tig * 2;
            *(float2*)&C[(size_t)row * N + col] =
                make_float2(acc[mt][nt][0], acc[mt][nt][1]);
            *(float2*)&C[(size_t)(row + 8) * N + col] =
                make_float2(acc[mt][nt][2], acc[mt][nt][3]);
        }
    }
}

// ---------------- RMSNorm + RoPE + cache scatter ----------------
__global__ __launch_bounds__(256) void rmsrope_kernel(
    float* __restrict__ qkv, const float* __restrict__ qw,
    const float* __restrict__ kw, const float* __restrict__ cosb,
    const float* __restrict__ sinb, const int* __restrict__ pos,
    float* __restrict__ ck, float* __restrict__ cv) {
    const int bt = blockIdx.x;
    const int b = bt / T_;
    const int t = bt % T_;
    const int lane = threadIdx.x & 31;
    const int w = threadIdx.x >> 5;
    const int p = pos[t];
    const float c = cosb[t * 32 + lane];
    const float s = sinb[t * 32 + lane];
    float* base = qkv + (size_t)bt * F_;

    for (int hh = w; hh < 48; hh += 8) {
        float* v = base + hh * 64;
        float x1 = v[lane];
        float x2 = v[lane + 32];
        if (hh < 40) {
            float ss = x1 * x1 + x2 * x2;
#pragma unroll
            for (int off = 16; off >= 1; off >>= 1)
                ss += __shfl_xor_sync(0xffffffffu, ss, off);
            float inv = rsqrtf(ss * (1.0f / 64.0f) + EPSV);
            const float* wgt = (hh < 32) ? qw : kw;
            float n1 = x1 * inv * wgt[lane];
            float n2 = x2 * inv * wgt[lane + 32];
            float r1 = n1 * c - n2 * s;
            float r2 = n2 * c + n1 * s;
            if (hh < 32) {
                v[lane] = r1;
                v[lane + 32] = r2;
            } else {
                float* dst = ck + (((size_t)b * S_ + p) * G_ + (hh - 32)) * 64;
                dst[lane] = r1;
                dst[lane + 32] = r2;
            }
        } else {
            float* dst = cv + (((size_t)b * S_ + p) * G_ + (hh - 40)) * 64;
            dst[lane] = x1;
            dst[lane + 32] = x2;
        }
    }
}

// ---------------- Tensor-core flash attention (tf32 warp-mma) -------------
#define KS_PAD 68
#define VS_PAD 72
#define PS_PAD 68
#define ATTN_SMEM ((64 * KS_PAD + 64 * VS_PAD + 128 * PS_PAD) * 4)

__global__ __launch_bounds__(256, 2) void attn_tc(
    const float* __restrict__ qkv, const float* __restrict__ ck,
    const float* __restrict__ cv, float* __restrict__ o) {
    extern __shared__ unsigned smu[];
    unsigned (*Ks)[KS_PAD] = (unsigned (*)[KS_PAD])smu;
    unsigned (*Vs)[VS_PAD] = (unsigned (*)[VS_PAD])(smu + 64 * KS_PAD);
    unsigned (*Ps)[PS_PAD] =
        (unsigned (*)[PS_PAD])(smu + 64 * KS_PAD + 64 * VS_PAD);

    const int bx = blockIdx.x;
    const int h = blockIdx.y;
    const int b = blockIdx.z;
    const int g = h >> 2;
    const int tid = threadIdx.x;
    const int wid = tid >> 5;
    const int lane = tid & 31;
    const int qid = lane >> 2;
    const int tig = lane & 3;
    const int t0 = bx * 128;
    const int wq = wid * 16;
    const int row0 = t0 + wq + qid;
    const int row1 = row0 + 8;

    unsigned qa[8][4];
    {
        const float* q0 = qkv + (size_t)(b * T_ + row0) * F_ + h * 64;
        const float* q1 = q0 + (size_t)8 * F_;
#pragma unroll
        for (int s = 0; s < 8; s++) {
            qa[s][0] = f2tf(0.125f * q0[8 * s + tig]);
            qa[s][1] = f2tf(0.125f * q1[8 * s + tig]);
            qa[s][2] = f2tf(0.125f * q0[8 * s + tig + 4]);
            qa[s][3] = f2tf(0.125f * q1[8 * s + tig + 4]);
        }
    }

    float oacc[8][4];
#pragma unroll
    for (int nt = 0; nt < 8; nt++)
#pragma unroll
        for (int j = 0; j < 4; j++) oacc[nt][j] = 0.0f;
    float m0 = -FLT_MAX, m1 = -FLT_MAX, l0 = 0.0f, l1 = 0.0f;

    const float* kb = ck + ((size_t)b * S_ * G_ + g) * 64;
    const float* vb = cv + ((size_t)b * S_ * G_ + g) * 64;
    const int nch = 2 * bx + 2;

    for (int scn = 0; scn < nch; scn++) {
        __syncthreads();
        {
            const float* kc = kb + (size_t)scn * 64 * (G_ * 64);
            const float* vc = vb + (size_t)scn * 64 * (G_ * 64);
            const int r = tid >> 4;
            const int c4 = (tid & 15) * 4;
#pragma unroll
            for (int rr = 0; rr < 4; rr++) {
                const int row = r + rr * 16;
                float4 k4 = *(const float4*)(kc + (size_t)row * (G_ * 64) + c4);
                float4 v4 = *(const float4*)(vc + (size_t)row * (G_ * 64) + c4);
                *(uint4*)&Ks[row][c4] =
                    make_uint4(f2tf(k4.x), f2tf(k4.y), f2tf(k4.z), f2tf(k4.w));
                *(uint4*)&Vs[row][c4] =
                    make_uint4(f2tf(v4.x), f2tf(v4.y), f2tf(v4.z), f2tf(v4.w));
            }
        }
        __syncthreads();

        if (scn * 64 <= t0 + wq + 15) {
            float sc[8][4];
#pragma unroll
            for (int nt = 0; nt < 8; nt++)
#pragma unroll
                for (int j = 0; j < 4; j++) sc[nt][j] = 0.0f;

#pragma unroll
            for (int s = 0; s < 8; s++) {
#pragma unroll
                for (int nt = 0; nt < 8; nt++) {
                    unsigned bf[2];
                    bf[0] = Ks[nt * 8 + qid][8 * s + tig];
                    bf[1] = Ks[nt * 8 + qid][8 * s + tig + 4];
                    mma_tf32(sc[nt], qa[s], bf);
                }
            }

            if (scn * 64 + 63 > t0 + wq) {
#pragma unroll
                for (int nt = 0; nt < 8; nt++) {
                    const int key0 = scn * 64 + nt * 8 + 2 * tig;
                    if (key0 > row0) sc[nt][0] = -1e30f;
                    if (key0 + 1 > row0) sc[nt][1] = -1e30f;
                    if (key0 > row1) sc[nt][2] = -1e30f;
                    if (key0 + 1 > row1) sc[nt][3] = -1e30f;
                }
            }

            float cm0 = -FLT_MAX, cm1 = -FLT_MAX;
#pragma unroll
            for (int nt = 0; nt < 8; nt++) {
                cm0 = fmaxf(cm0, fmaxf(sc[nt][0], sc[nt][1]));
                cm1 = fmaxf(cm1, fmaxf(sc[nt][2], sc[nt][3]));
            }
            cm0 = fmaxf(cm0, __shfl_xor_sync(0xffffffffu, cm0, 1));
            cm0 = fmaxf(cm0, __shfl_xor_sync(0xffffffffu, cm0, 2));
            cm1 = fmaxf(cm1, __shfl_xor_sync(0xffffffffu, cm1, 1));
            cm1 = fmaxf(cm1, __shfl_xor_sync(0xffffffffu, cm1, 2));
            const float mn0 = fmaxf(m0, cm0);
            const float mn1 = fmaxf(m1, cm1);
            const float a0 = __expf(m0 - mn0);
            const float a1 = __expf(m1 - mn1);
            float rs0 = 0.0f, rs1 = 0.0f;
#pragma unroll
            for (int nt = 0; nt < 8; nt++) {
                sc[nt][0] = __expf(sc[nt][0] - mn0);
                sc[nt][1] = __expf(sc[nt][1] - mn0);
                sc[nt][2] = __expf(sc[nt][2] - mn1);
                sc[nt][3] = __expf(sc[nt][3] - mn1);
                rs0 += sc[nt][0] + sc[nt][1];
                rs1 += sc[nt][2] + sc[nt][3];
            }
            rs0 += __shfl_xor_sync(0xffffffffu, rs0, 1);
            rs0 += __shfl_xor_sync(0xffffffffu, rs0, 2);
            rs1 += __shfl_xor_sync(0xffffffffu, rs1, 1);
            rs1 += __shfl_xor_sync(0xffffffffu, rs1, 2);
            l0 = l0 * a0 + rs0;
            l1 = l1 * a1 + rs1;
            m0 = mn0;
            m1 = mn1;
#pragma unroll
            for (int nt = 0; nt < 8; nt++) {
                oacc[nt][0] *= a0;
                oacc[nt][1] *= a0;
                oacc[nt][2] *= a1;
                oacc[nt][3] *= a1;
            }

#pragma unroll
            for (int nt = 0; nt < 8; nt++) {
                *(uint2*)&Ps[wq + qid][8 * nt + 2 * tig] =
                    make_uint2(f2tf(sc[nt][0]), f2tf(sc[nt][1]));
                *(uint2*)&Ps[wq + qid + 8][8 * nt + 2 * tig] =
                    make_uint2(f2tf(sc[nt][2]), f2tf(sc[nt][3]));
            }
            __syncwarp();

#pragma unroll
            for (int s = 0; s < 8; s++) {
                unsigned pa[4];
                pa[0] = Ps[wq + qid][8 * s + tig];
                pa[1] = Ps[wq + qid + 8][8 * s + tig];
                pa[2] = Ps[wq + qid][8 * s + tig + 4];
                pa[3] = Ps[wq + qid + 8][8 * s + tig + 4];
#pragma unroll
                for (int nt = 0; nt < 8; nt++) {
                    unsigned vf[2];
                    vf[0] = Vs[8 * s + tig][8 * nt + qid];
                    vf[1] = Vs[8 * s + tig + 4][8 * nt + qid];
                    mma_tf32(oacc[nt], pa, vf);
                }
            }
        }
    }

    const float i0 = 1.0f / l0;
    const float i1 = 1.0f / l1;
#pragma unroll
    for (int nt = 0; nt < 8; nt++) {
        const int col = h * 64 + 8 * nt + 2 * tig;
        *(float2*)&o[(size_t)(b * T_ + row0) * (H_ * D_) + col] =
            make_float2(oacc[nt][0] * i0, oacc[nt][1] * i0);
        *(float2*)&o[(size_t)(b * T_ + row1) * (H_ * D_) + col] =
            make_float2(oacc[nt][2] * i1, oacc[nt][3] * i1);
    }
}

// ---------------- launcher ----------------
extern "C" void kernel_launch(void* const* d_in, const int* in_sizes, int n_in,
                              void* d_out, int out_size) {
    const float* x = (const float*)d_in[0];
    const float* Wqkv = (const float*)d_in[1];
    const float* Wout = (const float*)d_in[2];
    const float* qw = (const float*)d_in[3];
    const float* kw = (const float*)d_in[4];
    const float* cosb = (const float*)d_in[5];
    const float* sinb = (const float*)d_in[6];
    const int* pos = (const int*)d_in[10];

    float* y = (float*)d_out;
    float* ck = y + (size_t)B_ * T_ * E_;
    float* cv = ck + (size_t)B_ * S_ * G_ * D_;

    void *pq, *po;
    cudaGetSymbolAddress(&pq, g_qkv);
    cudaGetSymbolAddress(&po, g_o);
    float* qkvbuf = (float*)pq;
    float* obuf = (float*)po;

    const size_t cacheBytes = sizeof(float) * (size_t)B_ * S_ * G_ * D_;
    cudaMemcpyAsync(ck, (const float*)d_in[8], cacheBytes,
                    cudaMemcpyDeviceToDevice, 0);
    cudaMemcpyAsync(cv, (const float*)d_in[9], cacheBytes,
                    cudaMemcpyDeviceToDevice, 0);

    cudaFuncSetAttribute(gemm_cp, cudaFuncAttributeMaxDynamicSharedMemorySize,
                         GM_SMEM);
    cudaFuncSetAttribute(attn_tc, cudaFuncAttributeMaxDynamicSharedMemorySize,
                         ATTN_SMEM);

    // 1) QKV projection
    gemm_cp<<<dim3(F_ / 128, (B_ * T_) / 128), 256, GM_SMEM>>>(
        x, Wqkv, qkvbuf, B_ * T_, F_, E_);

    // 2) rmsnorm + rope + cache scatter
    rmsrope_kernel<<<B_ * T_, 256>>>(qkvbuf, qw, kw, cosb, sinb, pos, ck, cv);

    // 3) tensor-core attention
    attn_tc<<<dim3(T_ / 128, H_, B_), 256, ATTN_SMEM>>>(qkvbuf, ck, cv, obuf);

    // 4) output projection
    gemm_cp<<<dim3(E_ / 128, (B_ * T_) / 128), 256, GM_SMEM>>>(
        obuf, Wout, y, B_ * T_, E_, E_);
}